// round 1
// baseline (speedup 1.0000x reference)
#include <cuda_runtime.h>
#include <cuda_bf16.h>

// Problem constants
#define D_MODEL 1024
#define BATCH   16
#define LQ      1024
#define NBE     256

// Scratch (allocation-free rule: __device__ globals)
__device__ float g_Q  [BATCH * LQ * D_MODEL];   // 64 MB  (also reused for pre-LN output)
__device__ float g_ENT[BATCH * NBE * D_MODEL];  // 16 MB
__device__ float g_S  [BATCH * LQ * NBE];       // 16 MB
__device__ float g_V  [BATCH * LQ * D_MODEL];   // 64 MB

// ---------------------------------------------------------------------------
// GEMM NT: C[M,N] = A[M,K] @ B[N,K]^T (+ bias), optional row-gather on A.
// All of M, N divisible by 128; K divisible by 8. Batched via blockIdx.z.
// GATHER: A row r comes from A[gidx[r], :]; gidx[r] < 0 -> whole output row 0.
// ---------------------------------------------------------------------------
template<bool GATHER, bool HAS_BIAS>
__global__ void __launch_bounds__(256) gemm_nt(
    const float* __restrict__ A, long sA,
    const float* __restrict__ B, long sB,
    float* __restrict__ C, long sC,
    int M, int N, int K,
    const float* __restrict__ bias,
    const int* __restrict__ gidx)
{
    const int BM = 128, BN = 128, BK = 8;
    __shared__ float As[BK][BM];
    __shared__ float Bs[BK][BN];

    A += (long)blockIdx.z * sA;
    B += (long)blockIdx.z * sB;
    C += (long)blockIdx.z * sC;

    const int bm  = blockIdx.y * BM;
    const int bn  = blockIdx.x * BN;
    const int tid = threadIdx.x;

    // Loader mapping: 128 rows x 8 cols tile; each thread owns one float4.
    const int lrow = tid >> 1;
    const int lcol = (tid & 1) * 4;

    const float* Arow;
    bool a_valid = true;
    {
        int grow = bm + lrow;
        if (GATHER) {
            int s = gidx[grow];
            if (s < 0) { a_valid = false; Arow = A; }
            else       { Arow = A + (long)s * K; }
        } else {
            Arow = A + (long)grow * K;
        }
    }
    const float* Brow = B + (long)(bn + lrow) * K;

    const int ty = tid >> 4;   // 0..15, M direction
    const int tx = tid & 15;   // 0..15, N direction

    float acc[8][8];
#pragma unroll
    for (int i = 0; i < 8; i++)
#pragma unroll
        for (int j = 0; j < 8; j++) acc[i][j] = 0.f;

    for (int k0 = 0; k0 < K; k0 += BK) {
        float4 av = a_valid ? *(const float4*)(Arow + k0 + lcol)
                            : make_float4(0.f, 0.f, 0.f, 0.f);
        float4 bv = *(const float4*)(Brow + k0 + lcol);
        As[lcol + 0][lrow] = av.x;
        As[lcol + 1][lrow] = av.y;
        As[lcol + 2][lrow] = av.z;
        As[lcol + 3][lrow] = av.w;
        Bs[lcol + 0][lrow] = bv.x;
        Bs[lcol + 1][lrow] = bv.y;
        Bs[lcol + 2][lrow] = bv.z;
        Bs[lcol + 3][lrow] = bv.w;
        __syncthreads();

#pragma unroll
        for (int kk = 0; kk < BK; kk++) {
            float ra[8], rb[8];
            *(float4*)(ra)     = *(const float4*)&As[kk][ty * 8];
            *(float4*)(ra + 4) = *(const float4*)&As[kk][ty * 8 + 4];
            *(float4*)(rb)     = *(const float4*)&Bs[kk][tx * 8];
            *(float4*)(rb + 4) = *(const float4*)&Bs[kk][tx * 8 + 4];
#pragma unroll
            for (int i = 0; i < 8; i++)
#pragma unroll
                for (int j = 0; j < 8; j++)
                    acc[i][j] += ra[i] * rb[j];
        }
        __syncthreads();
    }

    float bb[8];
    if (HAS_BIAS) {
#pragma unroll
        for (int j = 0; j < 8; j++) bb[j] = bias[bn + tx * 8 + j];
    }

#pragma unroll
    for (int i = 0; i < 8; i++) {
        int row = bm + ty * 8 + i;
        float rm = 1.f;
        if (GATHER) rm = (gidx[row] < 0) ? 0.f : 1.f;
        float out[8];
#pragma unroll
        for (int j = 0; j < 8; j++) {
            float v = acc[i][j];
            if (HAS_BIAS) v += bb[j];
            out[j] = v * rm;
        }
        float* cp = C + (long)row * N + bn + tx * 8;
        *(float4*)cp       = *(const float4*)out;
        *(float4*)(cp + 4) = *(const float4*)(out + 4);
    }
}

// ---------------------------------------------------------------------------
// GEMM NN: C[M,N] = A[M,K] @ B[K,N]. Batched. No bias. Divisibility as above.
// ---------------------------------------------------------------------------
__global__ void __launch_bounds__(256) gemm_nn(
    const float* __restrict__ A, long sA,
    const float* __restrict__ B, long sB,
    float* __restrict__ C, long sC,
    int M, int N, int K)
{
    const int BM = 128, BN = 128, BK = 8;
    __shared__ float As[BK][BM];
    __shared__ float Bs[BK][BN];

    A += (long)blockIdx.z * sA;
    B += (long)blockIdx.z * sB;
    C += (long)blockIdx.z * sC;

    const int bm  = blockIdx.y * BM;
    const int bn  = blockIdx.x * BN;
    const int tid = threadIdx.x;

    const int arow = tid >> 1;
    const int acol = (tid & 1) * 4;
    const float* Arow = A + (long)(bm + arow) * K;

    const int bkr = tid >> 5;          // 0..7 (K within tile)
    const int bnc = (tid & 31) * 4;    // 0..124 (N within tile)

    const int ty = tid >> 4;
    const int tx = tid & 15;

    float acc[8][8];
#pragma unroll
    for (int i = 0; i < 8; i++)
#pragma unroll
        for (int j = 0; j < 8; j++) acc[i][j] = 0.f;

    for (int k0 = 0; k0 < K; k0 += BK) {
        float4 av = *(const float4*)(Arow + k0 + acol);
        float4 bv = *(const float4*)(B + (long)(k0 + bkr) * N + bn + bnc);
        As[acol + 0][arow] = av.x;
        As[acol + 1][arow] = av.y;
        As[acol + 2][arow] = av.z;
        As[acol + 3][arow] = av.w;
        *(float4*)&Bs[bkr][bnc] = bv;
        __syncthreads();

#pragma unroll
        for (int kk = 0; kk < BK; kk++) {
            float ra[8], rb[8];
            *(float4*)(ra)     = *(const float4*)&As[kk][ty * 8];
            *(float4*)(ra + 4) = *(const float4*)&As[kk][ty * 8 + 4];
            *(float4*)(rb)     = *(const float4*)&Bs[kk][tx * 8];
            *(float4*)(rb + 4) = *(const float4*)&Bs[kk][tx * 8 + 4];
#pragma unroll
            for (int i = 0; i < 8; i++)
#pragma unroll
                for (int j = 0; j < 8; j++)
                    acc[i][j] += ra[i] * rb[j];
        }
        __syncthreads();
    }

#pragma unroll
    for (int i = 0; i < 8; i++) {
        int row = bm + ty * 8 + i;
        float* cp = C + (long)row * N + bn + tx * 8;
        *(float4*)cp       = *(const float4*)&acc[i][0];
        *(float4*)(cp + 4) = *(const float4*)&acc[i][4];
    }
}

// ---------------------------------------------------------------------------
// Masked softmax over NB=256 + post-softmax d^-0.5 scaling (in-place on S).
// One block (256 threads) per (b, y) row.
// ---------------------------------------------------------------------------
__global__ void softmax_mask(float* __restrict__ S, const int* __restrict__ idx)
{
    const int row = blockIdx.x;        // 0 .. B*L-1
    const int b   = row >> 10;         // row / LQ
    const int n   = threadIdx.x;
    const long off = (long)row * NBE + n;

    float s = S[off];
    if (idx[b * NBE + n] < 0) s = -100000.0f;  // masked: score was exactly 0 -> -1e5

    __shared__ float red[8];
    float m = s;
#pragma unroll
    for (int o = 16; o; o >>= 1) m = fmaxf(m, __shfl_xor_sync(0xffffffffu, m, o));
    if ((n & 31) == 0) red[n >> 5] = m;
    __syncthreads();
    float mall = red[0];
#pragma unroll
    for (int i = 1; i < 8; i++) mall = fmaxf(mall, red[i]);

    float e = expf(s - mall);
    __syncthreads();
    float t = e;
#pragma unroll
    for (int o = 16; o; o >>= 1) t += __shfl_xor_sync(0xffffffffu, t, o);
    if ((n & 31) == 0) red[n >> 5] = t;
    __syncthreads();
    float sum = 0.f;
#pragma unroll
    for (int i = 0; i < 8; i++) sum += red[i];

    S[off] = e * (0.03125f / sum);   // * d_model^-0.5 / sum
}

// ---------------------------------------------------------------------------
// Row LayerNorm over D=1024 (biased var, eps=1e-5). One block per row.
// ---------------------------------------------------------------------------
__global__ void layernorm_k(const float* __restrict__ X,
                            const float* __restrict__ g,
                            const float* __restrict__ b,
                            float* __restrict__ O)
{
    const int row = blockIdx.x;
    const int t   = threadIdx.x;
    const float* x = X + (long)row * D_MODEL;

    float4 v = *(const float4*)(x + t * 4);
    float s  = v.x + v.y + v.z + v.w;
    float sq = v.x * v.x + v.y * v.y + v.z * v.z + v.w * v.w;

    __shared__ float rs[8], rq[8];
#pragma unroll
    for (int o = 16; o; o >>= 1) {
        s  += __shfl_xor_sync(0xffffffffu, s,  o);
        sq += __shfl_xor_sync(0xffffffffu, sq, o);
    }
    if ((t & 31) == 0) { rs[t >> 5] = s; rq[t >> 5] = sq; }
    __syncthreads();
    float S = 0.f, Q = 0.f;
#pragma unroll
    for (int i = 0; i < 8; i++) { S += rs[i]; Q += rq[i]; }

    float mu  = S * (1.f / 1024.f);
    float var = Q * (1.f / 1024.f) - mu * mu;
    float inv = rsqrtf(var + 1e-5f);

    float4 gg = *(const float4*)(g + t * 4);
    float4 bb = *(const float4*)(b + t * 4);
    float4 o;
    o.x = (v.x - mu) * inv * gg.x + bb.x;
    o.y = (v.y - mu) * inv * gg.y + bb.y;
    o.z = (v.z - mu) * inv * gg.z + bb.z;
    o.w = (v.w - mu) * inv * gg.w + bb.w;
    *(float4*)(O + (long)row * D_MODEL + t * 4) = o;
}

// ---------------------------------------------------------------------------
extern "C" void kernel_launch(void* const* d_in, const int* in_sizes, int n_in,
                              void* d_out, int out_size)
{
    const float* query   = (const float*)d_in[0];
    const float* ent_emb = (const float*)d_in[1];
    const int*   idx     = (const int*)  d_in[2];
    // d_in[3] = max_entity_number (unused)
    const float* WQ_w = (const float*)d_in[4];
    const float* WQ_b = (const float*)d_in[5];
    const float* WK_w = (const float*)d_in[6];
    const float* WK_b = (const float*)d_in[7];
    const float* WO_w = (const float*)d_in[8];
    const float* WO_b = (const float*)d_in[9];
    const float* ln_g = (const float*)d_in[10];
    const float* ln_b = (const float*)d_in[11];
    float* out = (float*)d_out;

    float *Q, *ENT, *S, *V;
    cudaGetSymbolAddress((void**)&Q,   g_Q);
    cudaGetSymbolAddress((void**)&ENT, g_ENT);
    cudaGetSymbolAddress((void**)&S,   g_S);
    cudaGetSymbolAddress((void**)&V,   g_V);

    dim3 blk(256);

    // 1. Q = query @ WQ^T + WQ_b     (16384 x 1024 x 1024)
    gemm_nt<false, true><<<dim3(8, 128, 1), blk>>>(
        query, 0, WQ_w, 0, Q, 0, BATCH * LQ, D_MODEL, D_MODEL, WQ_b, nullptr);

    // 2. ENT = gather(ent_emb, idx) @ WK^T + WK_b, masked rows -> 0
    gemm_nt<true, true><<<dim3(8, 32, 1), blk>>>(
        ent_emb, 0, WK_w, 0, ENT, 0, BATCH * NBE, D_MODEL, D_MODEL, WK_b, idx);

    // 3. S[b] = Q[b] @ ENT[b]^T      (batched 1024 x 256 x 1024)
    gemm_nt<false, false><<<dim3(2, 8, BATCH), blk>>>(
        Q, (long)LQ * D_MODEL, ENT, (long)NBE * D_MODEL, S, (long)LQ * NBE,
        LQ, NBE, D_MODEL, nullptr, nullptr);

    // 4. masked softmax + scale (in place)
    softmax_mask<<<BATCH * LQ, NBE>>>(S, idx);

    // 5. V[b] = S[b] @ ENT[b]        (batched 1024 x 1024 x 256)
    gemm_nn<<<dim3(8, 8, BATCH), blk>>>(
        S, (long)LQ * NBE, ENT, (long)NBE * D_MODEL, V, (long)LQ * D_MODEL,
        LQ, D_MODEL, NBE);

    // 6. pre-LN output = V @ WO^T + WO_b (reuse g_Q as scratch)
    gemm_nt<false, true><<<dim3(8, 128, 1), blk>>>(
        V, 0, WO_w, 0, Q, 0, BATCH * LQ, D_MODEL, D_MODEL, WO_b, nullptr);

    // 7. LayerNorm -> d_out
    layernorm_k<<<BATCH * LQ, 256>>>(Q, ln_g, ln_b, out);
}

// round 3
// speedup vs baseline: 3.2183x; 3.2183x over previous
#include <cuda_runtime.h>
#include <cuda_bf16.h>
#include <cstdint>

// ---------------------------------------------------------------------------
// Problem constants
// ---------------------------------------------------------------------------
#define D_MODEL 1024
#define BATCH   16
#define LQ      1024
#define NBE     256

// ---------------------------------------------------------------------------
// Scratch (allocation-free rule: __device__ globals)
// ---------------------------------------------------------------------------
__device__ float g_G   [BATCH * NBE * D_MODEL];  // gathered entity embeddings
__device__ float g_ENT [BATCH * NBE * D_MODEL];  // K-projected entities (masked)
__device__ float g_ENTT[BATCH * NBE * D_MODEL];  // ENT^T per batch [D, NB]
__device__ float g_Q   [BATCH * LQ  * D_MODEL];  // Q proj / pre-LN scratch
__device__ float g_S   [BATCH * LQ  * NBE];      // scores / softmax weights
__device__ float g_V   [BATCH * LQ  * D_MODEL];  // attention output

// ---------------------------------------------------------------------------
// GEMM NT via mma.sync tf32 (sm_80+ path, works under plain sm_103 target).
// C[bz][M,N] = A[bz][M,K] @ B[bz][N,K]^T (+bias)(*rowmask)
// CTA tile 128x128, BK=32, warps 2x4 (warp tile 64x32), cp.async double buffer.
// M, N multiples of 128; K multiple of 32.
// ---------------------------------------------------------------------------
#define BKC 32
#define PADS 36                       // BK + 4 float padding -> conflict-free
#define TILE_FLOATS (128 * PADS)      // 4608 floats per matrix per stage
#define STAGE_FLOATS (2 * TILE_FLOATS)
#define GSMEM_BYTES (2 * STAGE_FLOATS * 4)   // 73728 B

__device__ __forceinline__ uint32_t f2tf32(float x) {
    uint32_t r;
    asm("cvt.rna.tf32.f32 %0, %1;" : "=r"(r) : "f"(x));
    return r;
}

__device__ __forceinline__ void cp16(uint32_t dst, const void* src) {
    asm volatile("cp.async.cg.shared.global [%0], [%1], 16;"
                 :: "r"(dst), "l"(src) : "memory");
}

template<bool HAS_BIAS, bool MASK>
__global__ void __launch_bounds__(256, 1) gemm_mma(
    const float* __restrict__ A, long sA,
    const float* __restrict__ B, long sB,
    float* __restrict__ C, long sC,
    int M, int N, int K,
    const float* __restrict__ bias,
    const int* __restrict__ rmask)
{
    extern __shared__ float sm[];
    const uint32_t smb = (uint32_t)__cvta_generic_to_shared(sm);

    const int tid  = threadIdx.x;
    const int wid  = tid >> 5;
    const int lane = tid & 31;
    const int wm   = wid >> 2;        // 0..1  (64-row slab)
    const int wn   = wid & 3;         // 0..3  (32-col slab)
    const int gq   = lane >> 2;       // group id 0..7
    const int tg   = lane & 3;        // thread-in-group 0..3

    const int mtile = blockIdx.y * 128;
    const int ntile = blockIdx.x * 128;
    const int bz    = blockIdx.z;
    A += (long)bz * sA;
    B += (long)bz * sB;
    C += (long)bz * sC;

    const int nch = K >> 5;

    float acc[4][4][4];
#pragma unroll
    for (int i = 0; i < 4; i++)
#pragma unroll
        for (int j = 0; j < 4; j++)
#pragma unroll
            for (int q = 0; q < 4; q++) acc[i][j][q] = 0.f;

    // ---- loader: 128 rows x 8 x 16B segments per matrix, 256 threads x 4 ----
    auto load_chunk = [&](int c, int s) {
        const int kofs = c * BKC;
#pragma unroll
        for (int i = 0; i < 4; i++) {
            const int t   = tid + i * 256;
            const int row = t >> 3;
            const int seg = (t & 7) * 4;
            uint32_t da = smb + (uint32_t)(s * STAGE_FLOATS + row * PADS + seg) * 4u;
            cp16(da, A + (long)(mtile + row) * K + kofs + seg);
            uint32_t db = smb + (uint32_t)(s * STAGE_FLOATS + TILE_FLOATS
                                           + row * PADS + seg) * 4u;
            cp16(db, B + (long)(ntile + row) * K + kofs + seg);
        }
    };

    load_chunk(0, 0);
    asm volatile("cp.async.commit_group;" ::: "memory");

    for (int c = 0; c < nch; c++) {
        const int s = c & 1;
        if (c + 1 < nch) {
            load_chunk(c + 1, s ^ 1);
            asm volatile("cp.async.commit_group;" ::: "memory");
            asm volatile("cp.async.wait_group 1;" ::: "memory");
        } else {
            asm volatile("cp.async.wait_group 0;" ::: "memory");
        }
        __syncthreads();

        const float* As = sm + s * STAGE_FLOATS;
        const float* Bs = As + TILE_FLOATS;

#pragma unroll
        for (int kk = 0; kk < 4; kk++) {
            const int kc = kk * 8 + tg;
            uint32_t af[4][4], bf[4][2];
#pragma unroll
            for (int mt = 0; mt < 4; mt++) {
                const int r0 = wm * 64 + mt * 16 + gq;
                af[mt][0] = f2tf32(As[r0 * PADS + kc]);
                af[mt][1] = f2tf32(As[(r0 + 8) * PADS + kc]);
                af[mt][2] = f2tf32(As[r0 * PADS + kc + 4]);
                af[mt][3] = f2tf32(As[(r0 + 8) * PADS + kc + 4]);
            }
#pragma unroll
            for (int nt = 0; nt < 4; nt++) {
                const int rb = wn * 32 + nt * 8 + gq;
                bf[nt][0] = f2tf32(Bs[rb * PADS + kc]);
                bf[nt][1] = f2tf32(Bs[rb * PADS + kc + 4]);
            }
#pragma unroll
            for (int mt = 0; mt < 4; mt++)
#pragma unroll
                for (int nt = 0; nt < 4; nt++) {
                    asm volatile(
                        "mma.sync.aligned.m16n8k8.row.col.f32.tf32.tf32.f32 "
                        "{%0,%1,%2,%3}, {%4,%5,%6,%7}, {%8,%9}, {%0,%1,%2,%3};"
                        : "+f"(acc[mt][nt][0]), "+f"(acc[mt][nt][1]),
                          "+f"(acc[mt][nt][2]), "+f"(acc[mt][nt][3])
                        : "r"(af[mt][0]), "r"(af[mt][1]),
                          "r"(af[mt][2]), "r"(af[mt][3]),
                          "r"(bf[nt][0]), "r"(bf[nt][1]));
                }
        }
        __syncthreads();
    }

    // ---- epilogue ----
#pragma unroll
    for (int mt = 0; mt < 4; mt++) {
        const int r0 = mtile + wm * 64 + mt * 16 + gq;   // rows r0, r0+8
        float rm0 = 1.f, rm1 = 1.f;
        if (MASK) {
            rm0 = (rmask[r0] < 0) ? 0.f : 1.f;
            rm1 = (rmask[r0 + 8] < 0) ? 0.f : 1.f;
        }
#pragma unroll
        for (int nt = 0; nt < 4; nt++) {
            const int col = ntile + wn * 32 + nt * 8 + tg * 2;
            float bx = 0.f, by = 0.f;
            if (HAS_BIAS) {
                float2 bb = *(const float2*)(bias + col);
                bx = bb.x; by = bb.y;
            }
            float2 o0, o1;
            o0.x = (acc[mt][nt][0] + bx) * rm0;
            o0.y = (acc[mt][nt][1] + by) * rm0;
            o1.x = (acc[mt][nt][2] + bx) * rm1;
            o1.y = (acc[mt][nt][3] + by) * rm1;
            *(float2*)(C + (long)r0 * N + col)       = o0;
            *(float2*)(C + (long)(r0 + 8) * N + col) = o1;
        }
    }
}

// ---------------------------------------------------------------------------
// Gather entity embeddings: G[r, :] = ent_emb[max(idx[r],0), :]
// ---------------------------------------------------------------------------
__global__ void gather_rows(const float* __restrict__ E,
                            const int* __restrict__ idx,
                            float* __restrict__ G)
{
    const int r = blockIdx.x;
    int s = idx[r];
    if (s < 0) s = 0;
    const float4* src = (const float4*)(E + (long)s * D_MODEL);
    float4* dst = (float4*)(G + (long)r * D_MODEL);
    for (int i = threadIdx.x; i < D_MODEL / 4; i += 128) dst[i] = src[i];
}

// ---------------------------------------------------------------------------
// Per-batch transpose: ENT[b] (NBE x D) -> ENTT[b] (D x NBE)
// ---------------------------------------------------------------------------
__global__ void transpose_ent(const float* __restrict__ in, float* __restrict__ out)
{
    __shared__ float t[32][33];
    const int b = blockIdx.z;
    const float* I = in  + (long)b * NBE * D_MODEL;
    float*       O = out + (long)b * NBE * D_MODEL;
    const int c0 = blockIdx.x * 32;
    const int r0 = blockIdx.y * 32;
    const int tx = threadIdx.x, ty = threadIdx.y;
#pragma unroll
    for (int i = 0; i < 32; i += 8)
        t[ty + i][tx] = I[(long)(r0 + ty + i) * D_MODEL + c0 + tx];
    __syncthreads();
#pragma unroll
    for (int i = 0; i < 32; i += 8)
        O[(long)(c0 + ty + i) * NBE + r0 + tx] = t[tx][ty + i];
}

// ---------------------------------------------------------------------------
// Masked softmax over NB=256 + post-softmax d^-0.5 scaling (in place).
// ---------------------------------------------------------------------------
__global__ void softmax_mask(float* __restrict__ S, const int* __restrict__ idx)
{
    const int row = blockIdx.x;
    const int b   = row >> 10;
    const int n   = threadIdx.x;
    const long off = (long)row * NBE + n;

    float s = S[off];
    if (idx[b * NBE + n] < 0) s = -100000.0f;

    __shared__ float red[8];
    float m = s;
#pragma unroll
    for (int o = 16; o; o >>= 1) m = fmaxf(m, __shfl_xor_sync(0xffffffffu, m, o));
    if ((n & 31) == 0) red[n >> 5] = m;
    __syncthreads();
    float mall = red[0];
#pragma unroll
    for (int i = 1; i < 8; i++) mall = fmaxf(mall, red[i]);

    float e = expf(s - mall);
    __syncthreads();
    float t = e;
#pragma unroll
    for (int o = 16; o; o >>= 1) t += __shfl_xor_sync(0xffffffffu, t, o);
    if ((n & 31) == 0) red[n >> 5] = t;
    __syncthreads();
    float sum = 0.f;
#pragma unroll
    for (int i = 0; i < 8; i++) sum += red[i];

    S[off] = e * (0.03125f / sum);
}

// ---------------------------------------------------------------------------
// Row LayerNorm over D=1024 (biased var, eps=1e-5).
// ---------------------------------------------------------------------------
__global__ void layernorm_k(const float* __restrict__ X,
                            const float* __restrict__ g,
                            const float* __restrict__ b,
                            float* __restrict__ O)
{
    const int row = blockIdx.x;
    const int t   = threadIdx.x;
    const float* x = X + (long)row * D_MODEL;

    float4 v = *(const float4*)(x + t * 4);
    float s  = v.x + v.y + v.z + v.w;
    float sq = v.x * v.x + v.y * v.y + v.z * v.z + v.w * v.w;

    __shared__ float rs[8], rq[8];
#pragma unroll
    for (int o = 16; o; o >>= 1) {
        s  += __shfl_xor_sync(0xffffffffu, s,  o);
        sq += __shfl_xor_sync(0xffffffffu, sq, o);
    }
    if ((t & 31) == 0) { rs[t >> 5] = s; rq[t >> 5] = sq; }
    __syncthreads();
    float S = 0.f, Q = 0.f;
#pragma unroll
    for (int i = 0; i < 8; i++) { S += rs[i]; Q += rq[i]; }

    float mu  = S * (1.f / 1024.f);
    float var = Q * (1.f / 1024.f) - mu * mu;
    float inv = rsqrtf(var + 1e-5f);

    float4 gg = *(const float4*)(g + t * 4);
    float4 bb = *(const float4*)(b + t * 4);
    float4 o;
    o.x = (v.x - mu) * inv * gg.x + bb.x;
    o.y = (v.y - mu) * inv * gg.y + bb.y;
    o.z = (v.z - mu) * inv * gg.z + bb.z;
    o.w = (v.w - mu) * inv * gg.w + bb.w;
    *(float4*)(O + (long)row * D_MODEL + t * 4) = o;
}

// ---------------------------------------------------------------------------
extern "C" void kernel_launch(void* const* d_in, const int* in_sizes, int n_in,
                              void* d_out, int out_size)
{
    const float* query   = (const float*)d_in[0];
    const float* ent_emb = (const float*)d_in[1];
    const int*   idx     = (const int*)  d_in[2];
    const float* WQ_w = (const float*)d_in[4];
    const float* WQ_b = (const float*)d_in[5];
    const float* WK_w = (const float*)d_in[6];
    const float* WK_b = (const float*)d_in[7];
    const float* WO_w = (const float*)d_in[8];
    const float* WO_b = (const float*)d_in[9];
    const float* ln_g = (const float*)d_in[10];
    const float* ln_b = (const float*)d_in[11];
    float* out = (float*)d_out;

    float *G, *ENT, *ENTT, *Q, *S, *V;
    cudaGetSymbolAddress((void**)&G,    g_G);
    cudaGetSymbolAddress((void**)&ENT,  g_ENT);
    cudaGetSymbolAddress((void**)&ENTT, g_ENTT);
    cudaGetSymbolAddress((void**)&Q,    g_Q);
    cudaGetSymbolAddress((void**)&S,    g_S);
    cudaGetSymbolAddress((void**)&V,    g_V);

    cudaFuncSetAttribute(gemm_mma<true,  false>,
        cudaFuncAttributeMaxDynamicSharedMemorySize, GSMEM_BYTES);
    cudaFuncSetAttribute(gemm_mma<true,  true>,
        cudaFuncAttributeMaxDynamicSharedMemorySize, GSMEM_BYTES);
    cudaFuncSetAttribute(gemm_mma<false, false>,
        cudaFuncAttributeMaxDynamicSharedMemorySize, GSMEM_BYTES);

    const int ML = BATCH * LQ;    // 16384
    const int MB = BATCH * NBE;   // 4096

    // 1. gather entity rows
    gather_rows<<<MB, 128>>>(ent_emb, idx, G);

    // 2. Q = query @ WQ^T + bQ
    gemm_mma<true, false><<<dim3(8, 128, 1), 256, GSMEM_BYTES>>>(
        query, 0, WQ_w, 0, Q, 0, ML, D_MODEL, D_MODEL, WQ_b, nullptr);

    // 3. ENT = (G @ WK^T + bK) * mask
    gemm_mma<true, true><<<dim3(8, 32, 1), 256, GSMEM_BYTES>>>(
        G, 0, WK_w, 0, ENT, 0, MB, D_MODEL, D_MODEL, WK_b, idx);

    // 4. ENTT[b] = ENT[b]^T
    transpose_ent<<<dim3(32, 8, BATCH), dim3(32, 8)>>>(ENT, ENTT);

    // 5. S[b] = Q[b] @ ENT[b]^T
    gemm_mma<false, false><<<dim3(2, 8, BATCH), 256, GSMEM_BYTES>>>(
        Q, (long)LQ * D_MODEL, ENT, (long)NBE * D_MODEL, S, (long)LQ * NBE,
        LQ, NBE, D_MODEL, nullptr, nullptr);

    // 6. masked softmax + d^-0.5 scale
    softmax_mask<<<BATCH * LQ, NBE>>>(S, idx);

    // 7. V[b] = S[b] @ ENTT[b]^T  (= S @ ENT)
    gemm_mma<false, false><<<dim3(8, 8, BATCH), 256, GSMEM_BYTES>>>(
        S, (long)LQ * NBE, ENTT, (long)NBE * D_MODEL, V, (long)LQ * D_MODEL,
        LQ, D_MODEL, NBE, nullptr, nullptr);

    // 8. pre-LN = V @ WO^T + bO (reuse Q)
    gemm_mma<true, false><<<dim3(8, 128, 1), 256, GSMEM_BYTES>>>(
        V, 0, WO_w, 0, Q, 0, ML, D_MODEL, D_MODEL, WO_b, nullptr);

    // 9. LayerNorm -> out
    layernorm_k<<<BATCH * LQ, 256>>>(Q, ln_g, ln_b, out);
}